// round 2
// baseline (speedup 1.0000x reference)
#include <cuda_runtime.h>

// Problem constants (fixed by the reference).
#define CC 128      // channels
#define WW 8        // hidden width
#define BB 8        // batch
#define TT 16000    // time
#define SPLIT 4     // T-splits per (b,c) row -> grid = B*C*SPLIT = 4096 blocks
#define TPB 128     // threads per block
// elements per block slice = TT/SPLIT = 4000 -> 1000 float4s

typedef unsigned long long u64;

// ---- packed f32x2 helpers (sm_100+) -------------------------------------
__device__ __forceinline__ u64 pack2(float lo, float hi) {
    u64 r;
    asm("mov.b64 %0, {%1, %2};" : "=l"(r) : "f"(lo), "f"(hi));
    return r;
}
__device__ __forceinline__ void unpack2(u64 v, float& lo, float& hi) {
    asm("mov.b64 {%0, %1}, %2;" : "=f"(lo), "=f"(hi) : "l"(v));
}
__device__ __forceinline__ u64 fma2(u64 a, u64 b, u64 c) {
    u64 d;
    asm("fma.rn.f32x2 %0, %1, %2, %3;" : "=l"(d) : "l"(a), "l"(b), "l"(c));
    return d;
}

// ELU: exp computed unconditionally (mixed-sign warps make predication useless),
// select via FSETP+FSEL (pred-as-data).
__device__ __forceinline__ float elu1(float y) {
    float e = __expf(y) - 1.0f;
    return (y > 0.0f) ? y : e;
}

struct ChanWeights {
    u64 w1p[4], b1p[4];       // layer1, packed over v-pairs
    u64 w2p[4][8];            // w2p[j][w] = {w2[2j][w], w2[2j+1][w]}
    u64 b2p[4];
    float w3r[8];
    float b3r;
};

__device__ __forceinline__ float mlp_elem(float xv, const ChanWeights& cw) {
    u64 xx = pack2(xv, xv);

    // layer 1: h1[v] = elu(w1[v]*x + b1[v]), 4 FFMA2
    float h1[WW];
#pragma unroll
    for (int j = 0; j < 4; j++) {
        u64 t = fma2(cw.w1p[j], xx, cw.b1p[j]);
        float y0, y1;
        unpack2(t, y0, y1);
        h1[2 * j]     = elu1(y0);
        h1[2 * j + 1] = elu1(y1);
    }

    // layer 2: h2[v] = elu(sum_w w2[v][w]*h1[w] + b2[v]), 32 FFMA2
    u64 acc[4];
#pragma unroll
    for (int j = 0; j < 4; j++) acc[j] = cw.b2p[j];
#pragma unroll
    for (int w = 0; w < WW; w++) {
        u64 hb = pack2(h1[w], h1[w]);
#pragma unroll
        for (int j = 0; j < 4; j++) acc[j] = fma2(cw.w2p[j][w], hb, acc[j]);
    }
    float h2[WW];
#pragma unroll
    for (int j = 0; j < 4; j++) {
        float y0, y1;
        unpack2(acc[j], y0, y1);
        h2[2 * j]     = elu1(y0);
        h2[2 * j + 1] = elu1(y1);
    }

    // layer 3: out = elu(sum_v w3[v]*h2[v] + b3), two FFMA chains for ILP
    float o0 = cw.b3r, o1 = 0.0f;
#pragma unroll
    for (int v = 0; v < WW; v += 2) {
        o0 = fmaf(cw.w3r[v],     h2[v],     o0);
        o1 = fmaf(cw.w3r[v + 1], h2[v + 1], o1);
    }
    return elu1(o0 + o1);
}

__global__ void __launch_bounds__(TPB, 2)
tnl_kernel(const float* __restrict__ x,
           const float* __restrict__ w1, const float* __restrict__ b1,
           const float* __restrict__ w2, const float* __restrict__ b2,
           const float* __restrict__ w3, const float* __restrict__ b3,
           float* __restrict__ out) {
    const int blk = blockIdx.x;
    const int s   = blk & (SPLIT - 1);
    const int row = blk >> 2;           // row = b*CC + c
    const int c   = row & (CC - 1);

    const float* w1c = w1 + c * WW;
    const float* b1c = b1 + c * WW;
    const float* w2c = w2 + c * WW * WW;   // [v][w]
    const float* b2c = b2 + c * WW;
    const float* w3c = w3 + c * WW;

    ChanWeights cw;
#pragma unroll
    for (int j = 0; j < 4; j++) {
        cw.w1p[j] = pack2(__ldg(w1c + 2 * j), __ldg(w1c + 2 * j + 1));
        cw.b1p[j] = pack2(__ldg(b1c + 2 * j), __ldg(b1c + 2 * j + 1));
        cw.b2p[j] = pack2(__ldg(b2c + 2 * j), __ldg(b2c + 2 * j + 1));
#pragma unroll
        for (int w = 0; w < WW; w++) {
            cw.w2p[j][w] = pack2(__ldg(w2c + (2 * j) * WW + w),
                                 __ldg(w2c + (2 * j + 1) * WW + w));
        }
    }
#pragma unroll
    for (int v = 0; v < WW; v++) cw.w3r[v] = __ldg(w3c + v);
    cw.b3r = __ldg(b3 + c);

    const size_t base = (size_t)row * TT + (size_t)s * (TT / SPLIT);
    const float4* __restrict__ xin  = (const float4*)(x + base);
    float4* __restrict__       oout = (float4*)(out + base);
    const int n4 = TT / SPLIT / 4;   // 1000

    for (int i = threadIdx.x; i < n4; i += TPB) {
        float4 v = __ldcs(xin + i);   // streaming read (touched once)
        float4 r;
        r.x = mlp_elem(v.x, cw);
        r.y = mlp_elem(v.y, cw);
        r.z = mlp_elem(v.z, cw);
        r.w = mlp_elem(v.w, cw);
        __stcs(oout + i, r);          // streaming write
    }
}

extern "C" void kernel_launch(void* const* d_in, const int* in_sizes, int n_in,
                              void* d_out, int out_size) {
    const float* x  = (const float*)d_in[0];
    const float* w1 = (const float*)d_in[1];
    const float* b1 = (const float*)d_in[2];
    const float* w2 = (const float*)d_in[3];
    const float* b2 = (const float*)d_in[4];
    const float* w3 = (const float*)d_in[5];
    const float* b3 = (const float*)d_in[6];
    float* out = (float*)d_out;

    dim3 grid(BB * CC * SPLIT);
    dim3 block(TPB);
    tnl_kernel<<<grid, block>>>(x, w1, b1, w2, b2, w3, b3, out);
}